// round 5
// baseline (speedup 1.0000x reference)
#include <cuda_runtime.h>

// QCNN closed form (see R0): layer k maps x_w <- prod_{j<=w} cos(x_j + theta_k_j),
// then out = sigmoid(x @ W + b).
//
// R5: occupancy is the binding constraint (issue 15.6% at 1024 warps; every
// per-thread depth optimization was neutral). Split each batch element across
// 4 lanes (wires 0-2 / 3-5 / 6-7 / 8-9): 4096 warps instead of 1024.
// Per layer: 2-3 cos per lane, local product, 3-shuffle width-4 segmented
// inclusive scan for the cross-lane prefix. Epilogue: per-lane partial x@W,
// width-4 butterfly reduce, lane 0 writes the float4.

#define NW 10
#define NLAYERS 6
#define FULLMASK 0xFFFFFFFFu

__global__ __launch_bounds__(128) void qcnn_kernel(
    const float* __restrict__ inputs,   // (B, 10)
    const float* __restrict__ thetas,   // (6, 10)
    const float* __restrict__ W,        // (10, 4)
    const float* __restrict__ bias,     // (4,)
    float* __restrict__ out,            // (B, 4)
    int B)
{
    int tid = blockIdx.x * blockDim.x + threadIdx.x;
    int e = tid >> 2;        // element index
    int l = tid & 3;         // lane within 4-lane group (warp-aligned)
    if (e >= B) return;      // B is a multiple of 8 => warp-uniform exit

    // Wire ranges per lane: l=0 -> {0,1,2}, l=1 -> {3,4,5}, l=2 -> {6,7}, l=3 -> {8,9}
    int start = (l < 2) ? 3 * l : 2 * l + 2;   // 0, 3, 6, 8
    bool has3 = (l < 2);

    const float* row = inputs + (size_t)e * NW + start;
    float x0 = __ldg(row + 0);
    float x1 = __ldg(row + 1);
    float x2 = has3 ? __ldg(row + 2) : 0.0f;

    #pragma unroll
    for (int k = 0; k < NLAYERS; k++) {
        const float* th = thetas + k * NW + start;
        float c0 = __cosf(x0 + __ldg(th + 0));
        float c1 = __cosf(x1 + __ldg(th + 1));
        float c2 = has3 ? __cosf(x2 + __ldg(th + 2)) : 1.0f;

        // Local prefix products within the lane.
        float p1 = c0 * c1;
        float p2 = p1 * c2;          // lane-total product

        // Width-4 inclusive scan of lane totals, then exclusive prefix E.
        float v = p2;
        float t = __shfl_up_sync(FULLMASK, v, 1, 4); if (l >= 1) v *= t;
        t       = __shfl_up_sync(FULLMASK, v, 2, 4); if (l >= 2) v *= t;
        float E = __shfl_up_sync(FULLMASK, v, 1, 4); if (l == 0) E = 1.0f;

        // Global prefix products for this lane's wires.
        x0 = E * c0;
        x1 = E * p1;
        x2 = E * p2;
    }

    // Epilogue: acc_o = bias_o + sum_w x_w * W[w][o], reduced across the 4 lanes.
    const float* wp = W + start * 4;
    float a0 = x0 * __ldg(wp + 0);
    float a1 = x0 * __ldg(wp + 1);
    float a2 = x0 * __ldg(wp + 2);
    float a3 = x0 * __ldg(wp + 3);
    a0 = fmaf(x1, __ldg(wp + 4), a0);
    a1 = fmaf(x1, __ldg(wp + 5), a1);
    a2 = fmaf(x1, __ldg(wp + 6), a2);
    a3 = fmaf(x1, __ldg(wp + 7), a3);
    if (has3) {
        a0 = fmaf(x2, __ldg(wp + 8), a0);
        a1 = fmaf(x2, __ldg(wp + 9), a1);
        a2 = fmaf(x2, __ldg(wp + 10), a2);
        a3 = fmaf(x2, __ldg(wp + 11), a3);
    }

    // Width-4 butterfly sum.
    #pragma unroll
    for (int s = 1; s < 4; s <<= 1) {
        a0 += __shfl_xor_sync(FULLMASK, a0, s, 4);
        a1 += __shfl_xor_sync(FULLMASK, a1, s, 4);
        a2 += __shfl_xor_sync(FULLMASK, a2, s, 4);
        a3 += __shfl_xor_sync(FULLMASK, a3, s, 4);
    }

    if (l == 0) {
        a0 += __ldg(bias + 0);
        a1 += __ldg(bias + 1);
        a2 += __ldg(bias + 2);
        a3 += __ldg(bias + 3);
        float4 r;
        r.x = __frcp_rn(1.0f + __expf(-a0));
        r.y = __frcp_rn(1.0f + __expf(-a1));
        r.z = __frcp_rn(1.0f + __expf(-a2));
        r.w = __frcp_rn(1.0f + __expf(-a3));
        reinterpret_cast<float4*>(out)[e] = r;
    }
}

extern "C" void kernel_launch(void* const* d_in, const int* in_sizes, int n_in,
                              void* d_out, int out_size) {
    const float* inputs = (const float*)d_in[0];  // (B, 10)
    const float* thetas = (const float*)d_in[1];  // (6, 10)
    const float* W      = (const float*)d_in[2];  // (10, 4)
    const float* bias   = (const float*)d_in[3];  // (4,)
    float* out = (float*)d_out;

    int B = in_sizes[0] / NW;        // 32768
    int nThreads = B * 4;            // 131072
    int threads = 128;
    int blocks = (nThreads + threads - 1) / threads;  // 1024
    qcnn_kernel<<<blocks, threads>>>(inputs, thetas, W, bias, out, B);
}

// round 6
// speedup vs baseline: 1.1392x; 1.1392x over previous
#include <cuda_runtime.h>

// QCNN closed form (see R0): layer k maps x_w <- prod_{j<=w} cos(x_j + theta_k_j),
// then out = sigmoid(x @ W + b).
//
// R6: model from R2..R5: time ~ total_instrs / issue%, issue% grows with warp
// count, instrs grow with decomposition width. R5 (4 lanes) overshot on bloat;
// R2 (1 lane) undershot on warps. This is the midpoint: 2 lanes per element
// (wires 0-4 / 5-9), 2048 warps, only ONE shuffle per layer (width-2 scan is
// a single total-exchange), epilogue split 2 outputs per lane.

#define NW 10
#define NLAYERS 6
#define FULLMASK 0xFFFFFFFFu

__global__ __launch_bounds__(256) void qcnn_kernel(
    const float* __restrict__ inputs,   // (B, 10)
    const float* __restrict__ thetas,   // (6, 10)
    const float* __restrict__ W,        // (10, 4)
    const float* __restrict__ bias,     // (4,)
    float* __restrict__ out,            // (B, 4)
    int B)
{
    int tid = blockIdx.x * blockDim.x + threadIdx.x;
    int e = tid >> 1;          // element index
    int l = tid & 1;           // half: wires [5l, 5l+5)
    if (e >= B) return;        // B*2 divisible by 256 => never taken, warp-uniform

    int base = l * 5;

    // Load this half's 5 features (consecutive lanes cover a contiguous 40B row).
    const float* row = inputs + (size_t)e * NW + base;
    float x0 = __ldg(row + 0);
    float x1 = __ldg(row + 1);
    float x2 = __ldg(row + 2);
    float x3 = __ldg(row + 3);
    float x4 = __ldg(row + 4);

    #pragma unroll
    for (int k = 0; k < NLAYERS; k++) {
        const float* th = thetas + k * NW + base;
        float c0 = __cosf(x0 + __ldg(th + 0));
        float c1 = __cosf(x1 + __ldg(th + 1));
        float c2 = __cosf(x2 + __ldg(th + 2));
        float c3 = __cosf(x3 + __ldg(th + 3));
        float c4 = __cosf(x4 + __ldg(th + 4));

        // Local inclusive prefix products (depth 4).
        float q0 = c0;
        float q1 = q0 * c1;
        float q2 = q1 * c2;
        float q3 = q2 * c3;
        float q4 = q3 * c4;

        // Exchange lane totals within the pair: one shuffle.
        float t = __shfl_xor_sync(FULLMASK, q4, 1, 2);
        float E = l ? t : 1.0f;    // lane 1 scales by lane 0's total

        x0 = E * q0;
        x1 = E * q1;
        x2 = E * q2;
        x3 = E * q3;
        x4 = E * q4;
    }

    // Epilogue: partial dot over this half's 5 wires for all 4 outputs.
    const float* wp = W + base * 4;
    float a0 = x0 * __ldg(wp + 0);
    float a1 = x0 * __ldg(wp + 1);
    float a2 = x0 * __ldg(wp + 2);
    float a3 = x0 * __ldg(wp + 3);
    a0 = fmaf(x1, __ldg(wp + 4),  a0);
    a1 = fmaf(x1, __ldg(wp + 5),  a1);
    a2 = fmaf(x1, __ldg(wp + 6),  a2);
    a3 = fmaf(x1, __ldg(wp + 7),  a3);
    a0 = fmaf(x2, __ldg(wp + 8),  a0);
    a1 = fmaf(x2, __ldg(wp + 9),  a1);
    a2 = fmaf(x2, __ldg(wp + 10), a2);
    a3 = fmaf(x2, __ldg(wp + 11), a3);
    a0 = fmaf(x3, __ldg(wp + 12), a0);
    a1 = fmaf(x3, __ldg(wp + 13), a1);
    a2 = fmaf(x3, __ldg(wp + 14), a2);
    a3 = fmaf(x3, __ldg(wp + 15), a3);
    a0 = fmaf(x4, __ldg(wp + 16), a0);
    a1 = fmaf(x4, __ldg(wp + 17), a1);
    a2 = fmaf(x4, __ldg(wp + 18), a2);
    a3 = fmaf(x4, __ldg(wp + 19), a3);

    // Pair-sum: after one xor-shuffle per accumulator both lanes hold totals.
    a0 += __shfl_xor_sync(FULLMASK, a0, 1, 2);
    a1 += __shfl_xor_sync(FULLMASK, a1, 1, 2);
    a2 += __shfl_xor_sync(FULLMASK, a2, 1, 2);
    a3 += __shfl_xor_sync(FULLMASK, a3, 1, 2);

    // Lane l produces outputs {2l, 2l+1}: 2 sigmoids each, one float2 store.
    float s0 = l ? a2 : a0;
    float s1 = l ? a3 : a1;
    s0 += __ldg(bias + 2 * l + 0);
    s1 += __ldg(bias + 2 * l + 1);

    float2 r;
    r.x = __frcp_rn(1.0f + __expf(-s0));
    r.y = __frcp_rn(1.0f + __expf(-s1));
    reinterpret_cast<float2*>(out)[e * 2 + l] = r;
}

extern "C" void kernel_launch(void* const* d_in, const int* in_sizes, int n_in,
                              void* d_out, int out_size) {
    const float* inputs = (const float*)d_in[0];  // (B, 10)
    const float* thetas = (const float*)d_in[1];  // (6, 10)
    const float* W      = (const float*)d_in[2];  // (10, 4)
    const float* bias   = (const float*)d_in[3];  // (4,)
    float* out = (float*)d_out;

    int B = in_sizes[0] / NW;        // 32768
    int nThreads = B * 2;            // 65536
    int threads = 256;
    int blocks = (nThreads + threads - 1) / threads;  // 256
    qcnn_kernel<<<blocks, threads>>>(inputs, thetas, W, bias, out, B);
}